// round 9
// baseline (speedup 1.0000x reference)
#include <cuda_runtime.h>
#include <math.h>
#include <stdint.h>

#define TT   1024
#define BB   512
#define DIN  128
#define HH   512
#define DOUT 128

#define NG   16
#define NS   8
#define MB   32
#define JS   64
#define NTHR 256

// smem byte offsets
#define WPB   528            // w row pitch bytes (66 u64)
#define VPB   272            // v row pitch bytes (34 u64)
#define VBUF  17408          // one v buffer: 64 rows * 272
#define W_OFF 0              // 320*528 = 168960
#define V_OFF 168960         // 2*17408 = 34816
#define R_OFF 203776         // red: 3*32*33 float2 = 25344
#define B_OFF 229120         // bias: 64*4
#define SMEM_TOTAL 229376

// k-pair-packed weights: W2[kq][j] = {w[j][2kq], w[j][2kq+1]}; kq<256 -> Wh, 256..319 -> Wx
__device__ unsigned long long g_W2[320 * 512];
// hidden state, k-pair-packed: g_h2[p][kq*512 + b] = {h[2kq][b], h[2kq+1][b]}
__device__ unsigned long long g_h2[2][256 * 512];
__device__ unsigned g_flag[NG][NS][32];

__global__ void prep_kernel(const float* __restrict__ Wh,
                            const float* __restrict__ Wx) {
    int i = blockIdx.x * blockDim.x + threadIdx.x;
    int stride = gridDim.x * blockDim.x;
    for (int idx = i; idx < 320 * 512; idx += stride) {
        int kq = idx >> 9;
        int j  = idx & 511;
        unsigned long long v;
        if (kq < 256)
            v = *reinterpret_cast<const unsigned long long*>(&Wh[j * HH + 2 * kq]);
        else
            v = *reinterpret_cast<const unsigned long long*>(&Wx[j * DIN + 2 * (kq - 256)]);
        g_W2[idx] = v;
    }
}

__global__ void zero_kernel() {
    int i = blockIdx.x * blockDim.x + threadIdx.x;
    int stride = gridDim.x * blockDim.x;
    unsigned long long* p = &g_h2[0][0];
    for (int k = i; k < 256 * 512; k += stride) p[k] = 0ull;
    unsigned* f = &g_flag[0][0][0];
    for (int k = i; k < NG * NS * 32; k += stride) f[k] = 0u;
}

__device__ __forceinline__ void lds_v2(uint64_t& a, uint64_t& b, uint32_t addr) {
    asm volatile("ld.shared.v2.u64 {%0,%1}, [%2];" : "=l"(a), "=l"(b) : "r"(addr));
}
#define FMA2(acc, w, h) \
    asm("fma.rn.f32x2 %0, %1, %2, %0;" : "+l"(acc) : "l"(w), "l"(h))

__device__ __forceinline__ float2 unpack2(uint64_t a) {
    float lo, hi;
    asm("mov.b64 {%0,%1}, %2;" : "=f"(lo), "=f"(hi) : "l"(a));
    return make_float2(lo, hi);
}

__global__ __launch_bounds__(NTHR, 1) void scan_kernel(
    const float* __restrict__ x,
    const float* __restrict__ bx,
    const float* __restrict__ bh,
    const float* __restrict__ Wy,
    const float* __restrict__ by,
    float* __restrict__ y)
{
    extern __shared__ char smem[];
    const uint32_t sb = (uint32_t)__cvta_generic_to_shared(smem);
    float2* redv  = reinterpret_cast<float2*>(smem + R_OFF);
    float* bias_s = reinterpret_cast<float*>(smem + B_OFF);

    const int tid = threadIdx.x;
    const int g   = blockIdx.x >> 3;
    const int s   = blockIdx.x & 7;

    // compute decode: quarter z, 8 j-threads, 8 m-threads
    const int z  = tid >> 6;          // 0..3 (k-split quarter)
    const int jt = tid & 7;           // j pairs at cols {2jt+16p}, p=0..3
    const int mt = (tid >> 3) & 7;    // m = 4*mt + mm (note: mt 0..7)

    // staging decode
    const int sr = tid >> 4;          // 0..15
    const int sc = tid & 15;          // 0..15 (16B units)
    // x staging decode
    const int xb  = tid & 31;
    const int xdc = tid >> 5;         // 0..7

    // ---- load weight slice into smem in CHUNK order (x rows first) ----
    for (int i = tid; i < 320 * 64; i += NTHR) {
        int wr = i >> 6, jl = i & 63;
        int w2row = (wr < 64) ? (256 + wr) : (wr - 64);
        reinterpret_cast<unsigned long long*>(smem + W_OFF)[wr * 66 + jl] =
            g_W2[(size_t)w2row * 512 + s * JS + jl];
    }
    if (tid < 64) bias_s[tid] = bx[s * JS + tid] + bh[s * JS + tid];
    __syncthreads();
    const float2 bias2 = reinterpret_cast<float2*>(bias_s)[jt + 8 * z];

    const float* __restrict__ xrow = &x[(size_t)(g * MB + xb) * TT * DIN];

    float4 pre[4];
    // ---- prologue: stage x(t=0) into buf 0 ----
    #pragma unroll
    for (int it = 0; it < 4; ++it)
        pre[it] = __ldg(reinterpret_cast<const float4*>(xrow + (xdc + 8 * it) * 4));
    #pragma unroll
    for (int it = 0; it < 4; ++it) {
        int dq = xdc + 8 * it;
        char* b0 = smem + V_OFF + (2 * dq) * VPB + xb * 8;
        *reinterpret_cast<float2*>(b0)       = make_float2(pre[it].x, pre[it].y);
        *reinterpret_cast<float2*>(b0 + VPB) = make_float2(pre[it].z, pre[it].w);
    }

    #define LDG_H(P, CH64)                                                       \
        do {                                                                     \
            const unsigned long long* hs = &g_h2[(P)][0];                        \
            _Pragma("unroll")                                                    \
            for (int it = 0; it < 4; ++it)                                       \
                pre[it] = __ldcg(reinterpret_cast<const float4*>(                \
                    hs + (size_t)((CH64) + sr + 16 * it) * 512 + g * MB + sc * 2)); \
        } while (0)

    #define STS_H(VB)                                                            \
        do {                                                                     \
            _Pragma("unroll")                                                    \
            for (int it = 0; it < 4; ++it)                                       \
                *reinterpret_cast<float4*>(smem + V_OFF + (VB) * VBUF +          \
                    (sr + 16 * it) * VPB + sc * 16) = pre[it];                   \
        } while (0)

    // wait for producer slices {2c, 2c+1} to have published step >= t
    #define WAIT2(C)                                                             \
        do {                                                                     \
            if (tid < 2) {                                                       \
                unsigned vv;                                                     \
                do {                                                             \
                    asm volatile("ld.acquire.gpu.global.u32 %0, [%1];"           \
                                 : "=r"(vv)                                      \
                                 : "l"(&g_flag[g][2 * (C) + tid][0]));           \
                } while (vv < (unsigned)t);                                      \
            }                                                                    \
        } while (0)

    #define COMPUTE(C, VB)                                                       \
        do {                                                                     \
            uint32_t wa = sb + (uint32_t)(W_OFF + ((C) * 64 + z * 16) * WPB + jt * 16); \
            uint32_t va = sb + (uint32_t)(V_OFF + (VB) * VBUF + (z * 16) * VPB + mt * 32); \
            _Pragma("unroll")                                                    \
            for (int qq = 0; qq < 16; ++qq) {                                    \
                uint64_t w00,w01,w10,w11,w20,w21,w30,w31,h0,h1,h2,h3;            \
                lds_v2(w00,w01, wa);                                             \
                lds_v2(w10,w11, wa + 128);                                       \
                lds_v2(w20,w21, wa + 256);                                       \
                lds_v2(w30,w31, wa + 384);                                       \
                lds_v2(h0,h1, va);                                               \
                lds_v2(h2,h3, va + 16);                                          \
                FMA2(acc[ 0],w00,h0); FMA2(acc[ 1],w00,h1); FMA2(acc[ 2],w00,h2); FMA2(acc[ 3],w00,h3); \
                FMA2(acc[ 4],w01,h0); FMA2(acc[ 5],w01,h1); FMA2(acc[ 6],w01,h2); FMA2(acc[ 7],w01,h3); \
                FMA2(acc[ 8],w10,h0); FMA2(acc[ 9],w10,h1); FMA2(acc[10],w10,h2); FMA2(acc[11],w10,h3); \
                FMA2(acc[12],w11,h0); FMA2(acc[13],w11,h1); FMA2(acc[14],w11,h2); FMA2(acc[15],w11,h3); \
                FMA2(acc[16],w20,h0); FMA2(acc[17],w20,h1); FMA2(acc[18],w20,h2); FMA2(acc[19],w20,h3); \
                FMA2(acc[20],w21,h0); FMA2(acc[21],w21,h1); FMA2(acc[22],w21,h2); FMA2(acc[23],w21,h3); \
                FMA2(acc[24],w30,h0); FMA2(acc[25],w30,h1); FMA2(acc[26],w30,h2); FMA2(acc[27],w30,h3); \
                FMA2(acc[28],w31,h0); FMA2(acc[29],w31,h1); FMA2(acc[30],w31,h2); FMA2(acc[31],w31,h3); \
                wa += WPB; va += VPB;                                            \
            }                                                                    \
        } while (0)

    int p = 0;
    for (int t = 0; t < TT; ++t) {
        uint64_t acc[32];
        #pragma unroll
        for (int i = 0; i < 32; ++i) acc[i] = 0ull;

        // chunk 0 gate + x compute
        WAIT2(0);
        __syncthreads();              // flags seen; x staged; weights ready
        LDG_H(p, 0);
        COMPUTE(0, p);                // x chunk (staged in buf p)
        STS_H(p ^ 1);

        WAIT2(1);
        __syncthreads();
        LDG_H(p, 64);
        COMPUTE(1, p ^ 1);
        STS_H(p);

        WAIT2(2);
        __syncthreads();
        LDG_H(p, 128);
        COMPUTE(2, p);
        STS_H(p ^ 1);

        WAIT2(3);
        __syncthreads();
        LDG_H(p, 192);
        COMPUTE(3, p ^ 1);
        STS_H(p);
        __syncthreads();

        // prefetch x(t+1), compute last chunk, stage x into buf p^1
        {
            const int tn = (t + 1 < TT) ? t + 1 : t;
            const float* xr = xrow + (size_t)tn * DIN;
            #pragma unroll
            for (int it = 0; it < 4; ++it)
                pre[it] = __ldg(reinterpret_cast<const float4*>(xr + (xdc + 8 * it) * 4));
        }
        COMPUTE(4, p);
        #pragma unroll
        for (int it = 0; it < 4; ++it) {
            int dq = xdc + 8 * it;
            char* b0 = smem + V_OFF + (p ^ 1) * VBUF + (2 * dq) * VPB + xb * 8;
            *reinterpret_cast<float2*>(b0)       = make_float2(pre[it].x, pre[it].y);
            *reinterpret_cast<float2*>(b0 + VPB) = make_float2(pre[it].z, pre[it].w);
        }

        // ---- distributed finalize: write partials for pp != z ----
        #pragma unroll
        for (int pp = 0; pp < 4; ++pp) {
            if (pp == z) continue;
            const int slot = ((z + 4 - pp) & 3) - 1;   // 0..2
            #pragma unroll
            for (int mm = 0; mm < 4; ++mm) {
                float2 v0 = unpack2(acc[pp * 8 + mm]);
                float2 v1 = unpack2(acc[pp * 8 + 4 + mm]);
                redv[(slot * 32 + 4 * mt + mm) * 33 + (jt + 8 * pp)] =
                    make_float2(v0.x + v0.y, v1.x + v1.y);
            }
        }
        __syncthreads();
        // finalize own pp == z block: combine, bias, tanh, packed u64 store
        {
            unsigned long long* hdst = &g_h2[p ^ 1][0];
            const size_t kqbase = (size_t)(32 * s + jt + 8 * z) * 512 + g * MB;
            #pragma unroll
            for (int mm = 0; mm < 4; ++mm) {
                float2 v0 = unpack2(acc[z * 8 + mm]);
                float2 v1 = unpack2(acc[z * 8 + 4 + mm]);
                float s0 = v0.x + v0.y + bias2.x;
                float s1 = v1.x + v1.y + bias2.y;
                #pragma unroll
                for (int r = 0; r < 3; ++r) {
                    float2 pr = redv[(r * 32 + 4 * mt + mm) * 33 + (jt + 8 * z)];
                    s0 += pr.x; s1 += pr.y;
                }
                float h0 = tanhf(s0), h1 = tanhf(s1);
                unsigned long long pk;
                asm("mov.b64 %0, {%1,%2};" : "=l"(pk) : "f"(h0), "f"(h1));
                __stcg(&hdst[kqbase + 4 * mt + mm], pk);
            }
        }
        __syncthreads();
        if (tid == 0) {
            asm volatile("fence.acq_rel.gpu;" ::: "memory");
            asm volatile("st.release.gpu.global.u32 [%0], %1;"
                         :: "l"(&g_flag[g][s][0]), "r"((unsigned)(t + 1))
                         : "memory");
        }
        p ^= 1;
    }

    // final: wait for all slices' last publish, then epilogue
    if (tid < NS) {
        unsigned v;
        do {
            asm volatile("ld.acquire.gpu.global.u32 %0, [%1];"
                         : "=r"(v) : "l"(&g_flag[g][tid][0]));
        } while (v < (unsigned)TT);
    }
    __syncthreads();

    // ---- epilogue: y = h_T @ Wy^T + by ; h_T packed in g_h2[0] ----
    const int o  = s * 16 + (tid & 15);
    const int me = tid >> 4;            // 0..15
    const unsigned long long* hfin = &g_h2[0][0];
    const unsigned long long* Wy2  = reinterpret_cast<const unsigned long long*>(Wy);
    uint64_t ya0 = 0ull, ya1 = 0ull;

    #pragma unroll
    for (int half = 0; half < 2; ++half) {
        __syncthreads();
        #pragma unroll
        for (int it = 0; it < 8; ++it) {
            int r = sr + 16 * it;
            float4 vv = __ldcg(reinterpret_cast<const float4*>(
                hfin + (size_t)(half * 128 + r) * 512 + g * MB + sc * 2));
            *reinterpret_cast<float4*>(smem + V_OFF + r * VPB + sc * 16) = vv;
        }
        __syncthreads();
        #pragma unroll 8
        for (int kq = 0; kq < 128; ++kq) {
            uint64_t h0 = *reinterpret_cast<uint64_t*>(
                smem + V_OFF + kq * VPB + me * 8);
            uint64_t h1 = *reinterpret_cast<uint64_t*>(
                smem + V_OFF + kq * VPB + (me + 16) * 8);
            unsigned long long wv = __ldg(&Wy2[(size_t)o * 256 + half * 128 + kq]);
            FMA2(ya0, wv, h0);
            FMA2(ya1, wv, h1);
        }
    }
    {
        float2 a0 = unpack2(ya0), a1 = unpack2(ya1);
        y[(size_t)(g * MB + me) * DOUT + o]      = by[o] + a0.x + a0.y;
        y[(size_t)(g * MB + me + 16) * DOUT + o] = by[o] + a1.x + a1.y;
    }
}

extern "C" void kernel_launch(void* const* d_in, const int* in_sizes, int n_in,
                              void* d_out, int out_size) {
    const float* x  = (const float*)d_in[0];
    const float* Wx = (const float*)d_in[1];
    const float* bx = (const float*)d_in[2];
    const float* Wh = (const float*)d_in[3];
    const float* bh = (const float*)d_in[4];
    const float* Wy = (const float*)d_in[5];
    const float* by = (const float*)d_in[6];
    float* y = (float*)d_out;

    cudaFuncSetAttribute(scan_kernel,
                         cudaFuncAttributeMaxDynamicSharedMemorySize, SMEM_TOTAL);

    prep_kernel<<<256, 256>>>(Wh, Wx);
    zero_kernel<<<256, 256>>>();
    scan_kernel<<<NG * NS, NTHR, SMEM_TOTAL>>>(x, bx, bh, Wy, by, y);
}

// round 10
// speedup vs baseline: 1.1181x; 1.1181x over previous
#include <cuda_runtime.h>
#include <math.h>
#include <stdint.h>

#define TT   1024
#define BB   512
#define DIN  128
#define HH   512
#define DOUT 128

#define NG   16
#define NS   8
#define MB   32
#define JS   64
#define NTHR 256

// smem byte offsets
#define WPB   528            // w row pitch bytes (66 u64)
#define VPB   272            // v row pitch bytes (34 u64)
#define VBUF  17408          // one v buffer: 64 rows * 272
#define W_OFF 0              // 320*528 = 168960
#define V_OFF 168960         // 2*17408 = 34816
#define R_OFF 203776         // red: 3*32*33 float2 = 25344
#define B_OFF 229120         // bias: 64*4
#define SMEM_TOTAL 229376

// k-pair-packed weights: W2[kq][j] = {w[j][2kq], w[j][2kq+1]}; kq<256 -> Wh, 256..319 -> Wx
__device__ unsigned long long g_W2[320 * 512];
// hidden state, k-pair-packed: g_h2[p][kq*512 + b] = {h[2kq][b], h[2kq+1][b]}
__device__ unsigned long long g_h2[2][256 * 512];
__device__ unsigned g_flag[NG][NS][32];

__global__ void prep_kernel(const float* __restrict__ Wh,
                            const float* __restrict__ Wx) {
    int i = blockIdx.x * blockDim.x + threadIdx.x;
    int stride = gridDim.x * blockDim.x;
    for (int idx = i; idx < 320 * 512; idx += stride) {
        int kq = idx >> 9;
        int j  = idx & 511;
        unsigned long long v;
        if (kq < 256)
            v = *reinterpret_cast<const unsigned long long*>(&Wh[j * HH + 2 * kq]);
        else
            v = *reinterpret_cast<const unsigned long long*>(&Wx[j * DIN + 2 * (kq - 256)]);
        g_W2[idx] = v;
    }
}

__global__ void zero_kernel() {
    int i = blockIdx.x * blockDim.x + threadIdx.x;
    int stride = gridDim.x * blockDim.x;
    unsigned long long* p = &g_h2[0][0];
    for (int k = i; k < 256 * 512; k += stride) p[k] = 0ull;
    unsigned* f = &g_flag[0][0][0];
    for (int k = i; k < NG * NS * 32; k += stride) f[k] = 0u;
}

__device__ __forceinline__ void lds_v2(uint64_t& a, uint64_t& b, uint32_t addr) {
    asm volatile("ld.shared.v2.u64 {%0,%1}, [%2];" : "=l"(a), "=l"(b) : "r"(addr));
}
#define FMA2(acc, w, h) \
    asm("fma.rn.f32x2 %0, %1, %2, %0;" : "+l"(acc) : "l"(w), "l"(h))

__device__ __forceinline__ float2 unpack2(uint64_t a) {
    float lo, hi;
    asm("mov.b64 {%0,%1}, %2;" : "=f"(lo), "=f"(hi) : "l"(a));
    return make_float2(lo, hi);
}

__global__ __launch_bounds__(NTHR, 1) void scan_kernel(
    const float* __restrict__ x,
    const float* __restrict__ bx,
    const float* __restrict__ bh,
    const float* __restrict__ Wy,
    const float* __restrict__ by,
    float* __restrict__ y)
{
    extern __shared__ char smem[];
    const uint32_t sb = (uint32_t)__cvta_generic_to_shared(smem);
    float2* redv  = reinterpret_cast<float2*>(smem + R_OFF);
    float* bias_s = reinterpret_cast<float*>(smem + B_OFF);

    const int tid = threadIdx.x;
    const int g   = blockIdx.x >> 3;
    const int s   = blockIdx.x & 7;

    // compute decode: quarter z, 8 j-threads, 8 m-threads
    const int z  = tid >> 6;          // 0..3 (k-split quarter)
    const int jt = tid & 7;           // j pairs at cols {2jt+16p}, p=0..3
    const int mt = (tid >> 3) & 7;    // m = 4*mt + mm

    // staging decode
    const int sr = tid >> 4;          // 0..15
    const int sc = tid & 15;          // 0..15 (16B units)
    // x staging decode
    const int xb  = tid & 31;
    const int xdc = tid >> 5;         // 0..7

    // ---- load weight slice into smem in CHUNK order (x rows first) ----
    for (int i = tid; i < 320 * 64; i += NTHR) {
        int wr = i >> 6, jl = i & 63;
        int w2row = (wr < 64) ? (256 + wr) : (wr - 64);
        reinterpret_cast<unsigned long long*>(smem + W_OFF)[wr * 66 + jl] =
            g_W2[(size_t)w2row * 512 + s * JS + jl];
    }
    if (tid < 64) bias_s[tid] = bx[s * JS + tid] + bh[s * JS + tid];

    const float* __restrict__ xrow = &x[(size_t)(g * MB + xb) * TT * DIN];

    float4 pre[4];
    // ---- prologue: stage x(t=0) into buf 0 ----
    #pragma unroll
    for (int it = 0; it < 4; ++it)
        pre[it] = __ldg(reinterpret_cast<const float4*>(xrow + (xdc + 8 * it) * 4));
    #pragma unroll
    for (int it = 0; it < 4; ++it) {
        int dq = xdc + 8 * it;
        char* b0 = smem + V_OFF + (2 * dq) * VPB + xb * 8;
        *reinterpret_cast<float2*>(b0)       = make_float2(pre[it].x, pre[it].y);
        *reinterpret_cast<float2*>(b0 + VPB) = make_float2(pre[it].z, pre[it].w);
    }
    __syncthreads();
    const float2 bias2 = reinterpret_cast<float2*>(bias_s)[jt + 8 * z];

    #define LDG_H(P, CH64)                                                       \
        do {                                                                     \
            const unsigned long long* hs = &g_h2[(P)][0];                        \
            _Pragma("unroll")                                                    \
            for (int it = 0; it < 4; ++it)                                       \
                pre[it] = __ldcg(reinterpret_cast<const float4*>(                \
                    hs + (size_t)((CH64) + sr + 16 * it) * 512 + g * MB + sc * 2)); \
        } while (0)

    #define STS_H(VB)                                                            \
        do {                                                                     \
            _Pragma("unroll")                                                    \
            for (int it = 0; it < 4; ++it)                                       \
                *reinterpret_cast<float4*>(smem + V_OFF + (VB) * VBUF +          \
                    (sr + 16 * it) * VPB + sc * 16) = pre[it];                   \
        } while (0)

    #define COMPUTE(C, VB)                                                       \
        do {                                                                     \
            uint32_t wa = sb + (uint32_t)(W_OFF + ((C) * 64 + z * 16) * WPB + jt * 16); \
            uint32_t va = sb + (uint32_t)(V_OFF + (VB) * VBUF + (z * 16) * VPB + mt * 32); \
            _Pragma("unroll")                                                    \
            for (int qq = 0; qq < 16; ++qq) {                                    \
                uint64_t w00,w01,w10,w11,w20,w21,w30,w31,h0,h1,h2,h3;            \
                lds_v2(w00,w01, wa);                                             \
                lds_v2(w10,w11, wa + 128);                                       \
                lds_v2(w20,w21, wa + 256);                                       \
                lds_v2(w30,w31, wa + 384);                                       \
                lds_v2(h0,h1, va);                                               \
                lds_v2(h2,h3, va + 16);                                          \
                FMA2(acc[ 0],w00,h0); FMA2(acc[ 1],w00,h1); FMA2(acc[ 2],w00,h2); FMA2(acc[ 3],w00,h3); \
                FMA2(acc[ 4],w01,h0); FMA2(acc[ 5],w01,h1); FMA2(acc[ 6],w01,h2); FMA2(acc[ 7],w01,h3); \
                FMA2(acc[ 8],w10,h0); FMA2(acc[ 9],w10,h1); FMA2(acc[10],w10,h2); FMA2(acc[11],w10,h3); \
                FMA2(acc[12],w11,h0); FMA2(acc[13],w11,h1); FMA2(acc[14],w11,h2); FMA2(acc[15],w11,h3); \
                FMA2(acc[16],w20,h0); FMA2(acc[17],w20,h1); FMA2(acc[18],w20,h2); FMA2(acc[19],w20,h3); \
                FMA2(acc[20],w21,h0); FMA2(acc[21],w21,h1); FMA2(acc[22],w21,h2); FMA2(acc[23],w21,h3); \
                FMA2(acc[24],w30,h0); FMA2(acc[25],w30,h1); FMA2(acc[26],w30,h2); FMA2(acc[27],w30,h3); \
                FMA2(acc[28],w31,h0); FMA2(acc[29],w31,h1); FMA2(acc[30],w31,h2); FMA2(acc[31],w31,h3); \
                wa += WPB; va += VPB;                                            \
            }                                                                    \
        } while (0)

    int p = 0;
    for (int t = 0; t < TT; ++t) {
        uint64_t acc[32];
        #pragma unroll
        for (int i = 0; i < 32; ++i) acc[i] = 0ull;

        LDG_H(p, 0);          // h chunk 1
        COMPUTE(0, p);        // x chunk (staged in buf p)
        STS_H(p ^ 1);
        __syncthreads();

        LDG_H(p, 64);
        COMPUTE(1, p ^ 1);
        STS_H(p);
        __syncthreads();

        LDG_H(p, 128);
        COMPUTE(2, p);
        STS_H(p ^ 1);
        __syncthreads();

        LDG_H(p, 192);
        COMPUTE(3, p ^ 1);
        STS_H(p);
        __syncthreads();

        // prefetch x(t+1), compute last chunk, stage x into buf p^1
        {
            const int tn = (t + 1 < TT) ? t + 1 : t;
            const float* xr = xrow + (size_t)tn * DIN;
            #pragma unroll
            for (int it = 0; it < 4; ++it)
                pre[it] = __ldg(reinterpret_cast<const float4*>(xr + (xdc + 8 * it) * 4));
        }
        COMPUTE(4, p);
        #pragma unroll
        for (int it = 0; it < 4; ++it) {
            int dq = xdc + 8 * it;
            char* b0 = smem + V_OFF + (p ^ 1) * VBUF + (2 * dq) * VPB + xb * 8;
            *reinterpret_cast<float2*>(b0)       = make_float2(pre[it].x, pre[it].y);
            *reinterpret_cast<float2*>(b0 + VPB) = make_float2(pre[it].z, pre[it].w);
        }

        // ---- distributed finalize: each quarter dumps partials for pp != z ----
        #pragma unroll
        for (int pp = 0; pp < 4; ++pp) {
            if (pp == z) continue;
            const int slot = ((z + 4 - pp) & 3) - 1;   // 0..2
            #pragma unroll
            for (int mm = 0; mm < 4; ++mm) {
                float2 v0 = unpack2(acc[pp * 8 + mm]);
                float2 v1 = unpack2(acc[pp * 8 + 4 + mm]);
                redv[(slot * 32 + 4 * mt + mm) * 33 + (jt + 8 * pp)] =
                    make_float2(v0.x + v0.y, v1.x + v1.y);
            }
        }
        __syncthreads();
        // each quarter finalizes its own pp == z block: combine, bias, tanh, store
        {
            unsigned long long* hdst = &g_h2[p ^ 1][0];
            const size_t kqbase = (size_t)(32 * s + jt + 8 * z) * 512 + g * MB;
            #pragma unroll
            for (int mm = 0; mm < 4; ++mm) {
                float2 v0 = unpack2(acc[z * 8 + mm]);
                float2 v1 = unpack2(acc[z * 8 + 4 + mm]);
                float s0 = v0.x + v0.y + bias2.x;
                float s1 = v1.x + v1.y + bias2.y;
                #pragma unroll
                for (int r = 0; r < 3; ++r) {
                    float2 pr = redv[(r * 32 + 4 * mt + mm) * 33 + (jt + 8 * z)];
                    s0 += pr.x; s1 += pr.y;
                }
                float h0 = tanhf(s0), h1 = tanhf(s1);
                unsigned long long pk;
                asm("mov.b64 %0, {%1,%2};" : "=l"(pk) : "f"(h0), "f"(h1));
                __stcg(&hdst[kqbase + 4 * mt + mm], pk);
            }
        }

        // ---- proven monolithic end-of-step barrier (R8 style) ----
        __syncthreads();
        if (tid == 0) {
            asm volatile("fence.acq_rel.gpu;" ::: "memory");
            asm volatile("st.release.gpu.global.u32 [%0], %1;"
                         :: "l"(&g_flag[g][s][0]), "r"((unsigned)(t + 1))
                         : "memory");
        }
        if (tid < NS) {
            const unsigned tgt = (unsigned)(t + 1);
            unsigned v;
            do {
                asm volatile("ld.acquire.gpu.global.u32 %0, [%1];"
                             : "=r"(v) : "l"(&g_flag[g][tid][0]));
            } while (v < tgt);
        }
        __syncthreads();
        p ^= 1;
    }

    // ---- epilogue: y = h_T @ Wy^T + by ; h_T packed in g_h2[0] ----
    const int o  = s * 16 + (tid & 15);
    const int me = tid >> 4;            // 0..15
    const unsigned long long* hfin = &g_h2[0][0];
    const unsigned long long* Wy2  = reinterpret_cast<const unsigned long long*>(Wy);
    uint64_t ya0 = 0ull, ya1 = 0ull;

    #pragma unroll
    for (int half = 0; half < 2; ++half) {
        __syncthreads();
        #pragma unroll
        for (int it = 0; it < 8; ++it) {
            int r = sr + 16 * it;
            float4 vv = __ldcg(reinterpret_cast<const float4*>(
                hfin + (size_t)(half * 128 + r) * 512 + g * MB + sc * 2));
            *reinterpret_cast<float4*>(smem + V_OFF + r * VPB + sc * 16) = vv;
        }
        __syncthreads();
        #pragma unroll 8
        for (int kq = 0; kq < 128; ++kq) {
            uint64_t h0 = *reinterpret_cast<uint64_t*>(
                smem + V_OFF + kq * VPB + me * 8);
            uint64_t h1 = *reinterpret_cast<uint64_t*>(
                smem + V_OFF + kq * VPB + (me + 16) * 8);
            unsigned long long wv = __ldg(&Wy2[(size_t)o * 256 + half * 128 + kq]);
            FMA2(ya0, wv, h0);
            FMA2(ya1, wv, h1);
        }
    }
    {
        float2 a0 = unpack2(ya0), a1 = unpack2(ya1);
        y[(size_t)(g * MB + me) * DOUT + o]      = by[o] + a0.x + a0.y;
        y[(size_t)(g * MB + me + 16) * DOUT + o] = by[o] + a1.x + a1.y;
    }
}

extern "C" void kernel_launch(void* const* d_in, const int* in_sizes, int n_in,
                              void* d_out, int out_size) {
    const float* x  = (const float*)d_in[0];
    const float* Wx = (const float*)d_in[1];
    const float* bx = (const float*)d_in[2];
    const float* Wh = (const float*)d_in[3];
    const float* bh = (const float*)d_in[4];
    const float* Wy = (const float*)d_in[5];
    const float* by = (const float*)d_in[6];
    float* y = (float*)d_out;

    cudaFuncSetAttribute(scan_kernel,
                         cudaFuncAttributeMaxDynamicSharedMemorySize, SMEM_TOTAL);

    prep_kernel<<<256, 256>>>(Wh, Wx);
    zero_kernel<<<256, 256>>>();
    scan_kernel<<<NG * NS, NTHR, SMEM_TOTAL>>>(x, bx, bh, Wy, by, y);
}